// round 15
// baseline (speedup 1.0000x reference)
#include <cuda_runtime.h>
#include <cuda_fp16.h>
#include <cstdint>

// ---------------------------------------------------------------------------
// CTRL transformer forward, GB300 (compute_103 -> mma.sync path).
// Round 15: MW=1 GEMM variant (Wo-proj, FF2) K-chunk 64 -> 128 (stride 272,
// conflict-free; 2 CTAs/SM retained). Doubles per-stage latency slack on the
// thinnest-tile GEMMs; FF2 stage count halves. MW=2 stays at chunk 64.
// Bit-identical accumulation. Everything else = round 14.
// ---------------------------------------------------------------------------

#define BB   2
#define SS   1024
#define DD   1280
#define HH   16
#define DHH  80
#define DFF  8192
#define LL   4
#define MM   (BB * SS)
#define D3   (3 * DD)
#define ALPHA 0.11180339887498949f

typedef __half hf;

// fp32 scratch
__device__ float g_x[MM * DD];
__device__ float g_bqkv[LL * 3 * DD];
// fp16 activations
__device__ hf g_n[MM * DD];
__device__ hf g_qkv[(size_t)MM * 3 * DD];
__device__ hf g_c[MM * DD];
__device__ hf g_h1[(size_t)MM * DFF];
// fp16 weights [N,K]
__device__ hf g_wqkv[(size_t)LL * 3 * DD * DD];
__device__ hf g_wo[LL * DD * DD];
__device__ hf g_w1[(size_t)LL * DD * DFF];
__device__ hf g_w2[(size_t)LL * DFF * DD];
__device__ int g_ids64;

// ---------------------------------------------------------------------------
__device__ __forceinline__ uint32_t smem_u32(const void* p) {
    uint32_t a;
    asm("{ .reg .u64 t; cvta.to.shared.u64 t, %1; cvt.u32.u64 %0, t; }"
        : "=r"(a) : "l"(p));
    return a;
}

__device__ __forceinline__ void ldsm_x4(uint32_t& r0, uint32_t& r1,
                                        uint32_t& r2, uint32_t& r3,
                                        uint32_t addr) {
    asm volatile("ldmatrix.sync.aligned.m8n8.x4.shared.b16 {%0,%1,%2,%3}, [%4];"
                 : "=r"(r0), "=r"(r1), "=r"(r2), "=r"(r3) : "r"(addr));
}

__device__ __forceinline__ void ldsm_x4_t(uint32_t& r0, uint32_t& r1,
                                          uint32_t& r2, uint32_t& r3,
                                          uint32_t addr) {
    asm volatile("ldmatrix.sync.aligned.m8n8.x4.trans.shared.b16 {%0,%1,%2,%3}, [%4];"
                 : "=r"(r0), "=r"(r1), "=r"(r2), "=r"(r3) : "r"(addr));
}

__device__ __forceinline__ void mma_f16(float* d, const uint32_t* a,
                                        uint32_t b0, uint32_t b1) {
    asm volatile(
        "mma.sync.aligned.m16n8k16.row.col.f32.f16.f16.f32 "
        "{%0,%1,%2,%3},{%4,%5,%6,%7},{%8,%9},{%0,%1,%2,%3};"
        : "+f"(d[0]), "+f"(d[1]), "+f"(d[2]), "+f"(d[3])
        : "r"(a[0]), "r"(a[1]), "r"(a[2]), "r"(a[3]), "r"(b0), "r"(b1));
}

__device__ __forceinline__ void cp16(uint32_t dst, const void* src, int sz) {
    asm volatile("cp.async.cg.shared.global [%0], [%1], 16, %2;"
                 :: "r"(dst), "l"(src), "r"(sz) : "memory");
}
#define CP_COMMIT() asm volatile("cp.async.commit_group;" ::: "memory")
#define CP_WAIT0()  asm volatile("cp.async.wait_group 0;" ::: "memory")
#define CP_WAIT1()  asm volatile("cp.async.wait_group 1;" ::: "memory")

__device__ __forceinline__ uint32_t pk2h(float a, float b) {
    __half2 h = __floats2half2_rn(a, b);
    return *reinterpret_cast<uint32_t*>(&h);
}

// ---------------------------------------------------------------------------
// detect + embed
// ---------------------------------------------------------------------------
__global__ void detect_kernel(const unsigned int* __restrict__ w) {
    __shared__ int any;
    if (threadIdx.x == 0) any = 0;
    __syncthreads();
    int loc = 0;
    for (int i = 2 * threadIdx.x + 1; i < 2048; i += 512)
        loc |= (w[i] != 0u);
    if (loc) atomicOr(&any, 1);
    __syncthreads();
    if (threadIdx.x == 0) g_ids64 = any ? 0 : 1;
}

__global__ void embed_kernel(const unsigned int* __restrict__ idw,
                             const float* __restrict__ emb,
                             float* __restrict__ x) {
    int idx = blockIdx.x * 256 + threadIdx.x;
    if (idx >= MM * DD) return;
    int d   = idx % DD;
    int row = idx / DD;
    int s   = row & (SS - 1);
    int id  = g_ids64 ? (int)idw[2 * row] : (int)idw[row];
    float val = emb[(long long)id * DD + d] * 35.77708763999664f;
    int m = (d < 640) ? d : d - 640;
    float rate = expf(-0.014391156831212787f * (float)m);
    float ang  = (float)s * rate;
    val += (d < 640) ? sinf(ang) : cosf(ang);
    x[idx] = val;
}

// ---------------------------------------------------------------------------
// weight convert+transpose: fp32 [K,N] -> fp16 [N,K]; 64x64 tiles
// ---------------------------------------------------------------------------
__global__ void __launch_bounds__(256)
wtrans_kernel(const float* __restrict__ W, hf* __restrict__ oh,
              int K, int N, size_t ostride) {
    W  += (size_t)blockIdx.z * K * N;
    oh += (size_t)blockIdx.z * ostride;
    __shared__ float tf[64][65];
    const int n0 = blockIdx.x * 64, k0 = blockIdx.y * 64;
    const int tx = threadIdx.x & 15;
    const int ty = threadIdx.x >> 4;
#pragma unroll
    for (int i = 0; i < 4; i++) {
        const int r = ty + 16 * i;
        float4 v = *(const float4*)(W + (long long)(k0 + r) * N + n0 + tx * 4);
        tf[r][tx * 4 + 0] = v.x;
        tf[r][tx * 4 + 1] = v.y;
        tf[r][tx * 4 + 2] = v.z;
        tf[r][tx * 4 + 3] = v.w;
    }
    __syncthreads();
#pragma unroll
    for (int i = 0; i < 4; i++) {
        const int n = ty + 16 * i;
        uint2 pk = make_uint2(
            pk2h(tf[tx * 4 + 0][n], tf[tx * 4 + 1][n]),
            pk2h(tf[tx * 4 + 2][n], tf[tx * 4 + 3][n]));
        *(uint2*)(oh + (long long)(n0 + n) * K + k0 + tx * 4) = pk;
    }
}

// pack qkv bias: [L][3840] from bq,bk,bv
__global__ void packb_kernel(const float* __restrict__ bq,
                             const float* __restrict__ bk,
                             const float* __restrict__ bv,
                             float* __restrict__ o) {
    int i = blockIdx.x * 256 + threadIdx.x;
    if (i >= LL * 3 * DD) return;
    int l = i / (3 * DD), j = i % (3 * DD);
    float v = (j < DD) ? bq[l * DD + j]
            : (j < 2 * DD) ? bk[l * DD + j - DD]
            : bv[l * DD + j - 2 * DD];
    o[i] = v;
}

// ---------------------------------------------------------------------------
// LayerNorm: 160 threads x 8 values
// ---------------------------------------------------------------------------
template <bool HOUT>
__global__ void __launch_bounds__(160)
layernorm_kernel(const float* __restrict__ x,
                 float* __restrict__ o, hf* __restrict__ oh,
                 const float* __restrict__ g, const float* __restrict__ b) {
    const int row = blockIdx.x;
    const int t   = threadIdx.x;
    const float4* xr = (const float4*)(x + (long long)row * DD);
    __shared__ float red[5];

    float4 a0 = xr[2 * t], a1 = xr[2 * t + 1];
    float v[8] = {a0.x, a0.y, a0.z, a0.w, a1.x, a1.y, a1.z, a1.w};
    float s = 0.0f;
#pragma unroll
    for (int i = 0; i < 8; i++) s += v[i];
#pragma unroll
    for (int of = 16; of; of >>= 1) s += __shfl_xor_sync(0xffffffffu, s, of);
    if ((t & 31) == 0) red[t >> 5] = s;
    __syncthreads();
    float mu = (red[0] + red[1] + red[2] + red[3] + red[4]) * (1.0f / 1280.0f);
    __syncthreads();
    float q = 0.0f;
#pragma unroll
    for (int i = 0; i < 8; i++) { float dv = v[i] - mu; q += dv * dv; }
#pragma unroll
    for (int of = 16; of; of >>= 1) q += __shfl_xor_sync(0xffffffffu, q, of);
    if ((t & 31) == 0) red[t >> 5] = q;
    __syncthreads();
    float var = (red[0] + red[1] + red[2] + red[3] + red[4]) * (1.0f / 1280.0f);
    float rstd = rsqrtf(var + 1e-6f);

    const float4* gp = (const float4*)(g + 8 * t);
    const float4* bp = (const float4*)(b + 8 * t);
    float4 g0 = gp[0], g1 = gp[1], b0 = bp[0], b1 = bp[1];
    float gg[8] = {g0.x, g0.y, g0.z, g0.w, g1.x, g1.y, g1.z, g1.w};
    float bb[8] = {b0.x, b0.y, b0.z, b0.w, b1.x, b1.y, b1.z, b1.w};

    float y[8];
#pragma unroll
    for (int i = 0; i < 8; i++) y[i] = (v[i] - mu) * rstd * gg[i] + bb[i];

    if (HOUT) {
        uint4 pk = make_uint4(pk2h(y[0], y[1]), pk2h(y[2], y[3]),
                              pk2h(y[4], y[5]), pk2h(y[6], y[7]));
        ((uint4*)(oh + (long long)row * DD))[t] = pk;
    } else {
        float4* op = (float4*)(o + (long long)row * DD);
        op[2 * t]     = make_float4(y[0], y[1], y[2], y[3]);
        op[2 * t + 1] = make_float4(y[4], y[5], y[6], y[7]);
    }
}

// ---------------------------------------------------------------------------
// Flash attention (unchanged): 144 balanced CTAs, v via ldmatrix.trans.
// ---------------------------------------------------------------------------
#define FQ_OF 0
#define FK_OF 22528
#define FV_OF 67584
#define SMEM_FLASH 112640

__global__ void __launch_bounds__(256, 1)
flash_kernel(const hf* __restrict__ qkv, hf* __restrict__ ctx) {
    const int z = blockIdx.x;
    int np, qts[2], bhs[2];
    if (z < 32)       { np = 1; bhs[0] = z; qts[0] = 7; bhs[1] = 0; qts[1] = 0; }
    else if (z < 128) { int gi = z >> 5; int bh = z & 31;
                        np = 2; bhs[0] = bhs[1] = bh;
                        qts[0] = 7 - gi; qts[1] = gi - 1; }
    else              { int i = z - 128;
                        np = 2; bhs[0] = 2 * i; bhs[1] = 2 * i + 1;
                        qts[0] = qts[1] = 3; }

    extern __shared__ char sm[];
    const uint32_t smb = smem_u32(sm);

    const int tid = threadIdx.x;
    const int wid = tid >> 5, lane = tid & 31;
    const int g = lane >> 2, t = lane & 3;
    const int lrow = lane & 15, lcol = (lane >> 4) << 3;
    const int wr0 = wid * 16;
    const int vrow = ((lane >> 3) & 1) * 8 + (lane & 7);
    const int vcol = (lane >> 4) << 3;

    for (int pass = 0; pass < np; pass++) {
        const int qt = qts[pass];
        const int bh = bhs[pass];
        const int zb = bh >> 4, zh = bh & 15;

        const hf* kbase = qkv + (long long)zb * SS * D3 + DD + zh * DHH;
        const hf* vbase = kbase + DD;

        auto fillKV = [&](int j) {
            const uint32_t kb = smb + FK_OF + (j & 1) * 22528;
            const uint32_t vb = smb + FV_OF + (j & 1) * 22528;
            const long long ro = (long long)(j * 128) * D3;
            for (int i = tid; i < 1280; i += 256) {
                int r = i / 10, c = i % 10;
                const long long go = ro + (long long)r * D3 + c * 8;
                cp16(kb + r * 176 + c * 16, kbase + go, 16);
                cp16(vb + r * 176 + c * 16, vbase + go, 16);
            }
        };

        const long long qtok0 = (long long)zb * SS + qt * 128;
        const hf* qbase = qkv + qtok0 * D3 + zh * DHH;
        const int qrow = qt * 128 + wr0 + g;

        for (int i = tid; i < 1280; i += 256) {
            int r = i / 10, c = i % 10;
            cp16(smb + FQ_OF + r * 176 + c * 16,
                 qbase + (long long)r * D3 + c * 8, 16);
        }
        fillKV(0); CP_COMMIT();
        if (qt >= 1) { fillKV(1); CP_COMMIT(); }

        float o[10][4] = {};
        float mx0 = -3.4e38f, mx1 = -3.4e38f, sum0 = 0.0f, sum1 = 0.0f;

        for (int j = 0; j <= qt; j++) {
            if (j + 1 <= qt) CP_WAIT1(); else CP_WAIT0();
            __syncthreads();

            const uint32_t kb = smb + FK_OF + (j & 1) * 22528;
            const uint32_t vb = smb + FV_OF + (j & 1) * 22528;

            float s[16][4] = {};
#pragma unroll
            for (int kc = 0; kc < 5; kc++) {
                uint32_t a[4];
                ldsm_x4(a[0], a[1], a[2], a[3],
                        smb + FQ_OF + (wr0 + lrow) * 176 + (kc * 16 + lcol) * 2);
#pragma unroll
                for (int nfp = 0; nfp < 8; nfp++) {
                    uint32_t b[4];
                    ldsm_x4(b[0], b[1], b[2], b[3],
                            kb + (nfp * 16 + lrow) * 176 + (kc * 16 + lcol) * 2);
                    mma_f16(s[2 * nfp],     a, b[0], b[2]);
                    mma_f16(s[2 * nfp + 1], a, b[1], b[3]);
                }
            }

            const bool diag = (j == qt);
            const int kb0 = j * 128;
            float tm0 = -3.4e38f, tm1 = -3.4e38f;
#pragma unroll
            for (int nf = 0; nf < 16; nf++) {
                const int col = kb0 + nf * 8 + 2 * t;
#pragma unroll
                for (int e = 0; e < 2; e++) {
                    float v0 = s[nf][e]     * ALPHA;
                    float v1 = s[nf][e + 2] * ALPHA;
                    if (diag) {
                        if (col + e > qrow)     v0 = -3.4e38f;
                        if (col + e > qrow + 8) v1 = -3.4e38f;
                    }
                    s[nf][e] = v0; s[nf][e + 2] = v1;
                    tm0 = fmaxf(tm0, v0); tm1 = fmaxf(tm1, v1);
                }
            }
            tm0 = fmaxf(tm0, __shfl_xor_sync(0xffffffffu, tm0, 1));
            tm0 = fmaxf(tm0, __shfl_xor_sync(0xffffffffu, tm0, 2));
            tm1 = fmaxf(tm1, __shfl_xor_sync(0xffffffffu, tm1, 1));
            tm1 = fmaxf(tm1, __shfl_xor_sync(0xffffffffu, tm1, 2));

            const float nmx0 = fmaxf(mx0, tm0), nmx1 = fmaxf(mx1, tm1);
            const float sc0 = expf(mx0 - nmx0), sc1 = expf(mx1 - nmx1);
            mx0 = nmx0; mx1 = nmx1;

            uint32_t pA[8][4];
            float ts0 = 0.0f, ts1 = 0.0f;
#pragma unroll
            for (int nf = 0; nf < 16; nf++) {
                float e0 = expf(s[nf][0] - mx0);
                float e1 = expf(s[nf][1] - mx0);
                float e2 = expf(s[nf][2] - mx1);
                float e3 = expf(s[nf][3] - mx1);
                ts0 += e0 + e1; ts1 += e2 + e3;
                const int kc2 = nf >> 1, hi = nf & 1;
                pA[kc2][hi * 2]     = pk2h(e0, e1);
                pA[kc2][hi * 2 + 1] = pk2h(e2, e3);
            }
            ts0 += __shfl_xor_sync(0xffffffffu, ts0, 1);
            ts0 += __shfl_xor_sync(0xffffffffu, ts0, 2);
            ts1 += __shfl_xor_sync(0xffffffffu, ts1, 1);
            ts1 += __shfl_xor_sync(0xffffffffu, ts1, 2);
            sum0 = sum0 * sc0 + ts0;
            sum1 = sum1 * sc1 + ts1;

#pragma unroll
            for (int nf = 0; nf < 10; nf++) {
                o[nf][0] *= sc0; o[nf][1] *= sc0;
                o[nf][2] *= sc1; o[nf][3] *= sc1;
            }
#pragma unroll
            for (int nfp2 = 0; nfp2 < 5; nfp2++) {
#pragma unroll
                for (int kc2 = 0; kc2 < 8; kc2++) {
                    uint32_t b[4];
                    ldsm_x4_t(b[0], b[1], b[2], b[3],
                              vb + (kc2 * 16 + vrow) * 176
                                 + (nfp2 * 16 + vcol) * 2);
                    mma_f16(o[2 * nfp2],     pA[kc2], b[0], b[1]);
                    mma_f16(o[2 * nfp2 + 1], pA[kc2], b[2], b[3]);
                }
            }

            __syncthreads();
            if (j + 2 <= qt) { fillKV(j + 2); CP_COMMIT(); }
        }

        const float inv0 = 1.0f / sum0, inv1 = 1.0f / sum1;
        const long long r0 = (qtok0 + wr0 + g) * DD + zh * DHH;
        const long long r1 = r0 + 8LL * DD;
#pragma unroll
        for (int nf = 0; nf < 10; nf++) {
            const int d = nf * 8 + 2 * t;
            *(uint32_t*)(ctx + r0 + d) = pk2h(o[nf][0] * inv0, o[nf][1] * inv0);
            *(uint32_t*)(ctx + r1 + d) = pk2h(o[nf][2] * inv1, o[nf][3] * inv1);
        }
    }
}

// ---------------------------------------------------------------------------
// fp16 GEMM, templated K-chunk KC (64 -> stride 176, 128 -> stride 272;
// both conflict-free for ldsm). C = alpha*A@B^T [+bias][relu][+resid].
// All K values are multiples of KC in every call.
// ---------------------------------------------------------------------------
template <int MW, int NW, int KC, bool RELU, bool HOUT>
__global__ void __launch_bounds__(MW * NW * 32)
gemm1(const hf* __restrict__ A, const hf* __restrict__ B,
      float* __restrict__ C, hf* __restrict__ Ch,
      const float* __restrict__ bias, const float* __restrict__ resid,
      int M, int N, int K, int lda, int ldb, int ldc, float alpha) {
    constexpr int AR   = 64 * MW;
    constexpr int BR   = 64 * NW;
    constexpr int BD   = MW * NW * 32;
    constexpr int RSTR = (KC == 64) ? 176 : 272;   // bytes per row
    constexpr int CH   = KC / 8;                   // 16B chunks per row
    constexpr int A_OF = 0;
    constexpr int B_OF = AR * RSTR;
    constexpr int STG  = (AR + BR) * RSTR;

    const int m0 = blockIdx.y * AR;
    const int n0 = blockIdx.x * BR;

    extern __shared__ char sm[];
    const uint32_t smb = smem_u32(sm);

    const int tid  = threadIdx.x;
    const int wid  = tid >> 5;
    const int lane = tid & 31;
    const int wm   = wid / NW;
    const int wn   = wid % NW;

    const int nst = K / KC;

    auto fill = [&](int s) {
        const uint32_t sb = smb + (uint32_t)((s & 1) * STG);
        const int kbase = s * KC;
#pragma unroll
        for (int i = tid; i < AR * CH; i += BD) {
            const int row = i / CH, c = i % CH;
            const long long go = (long long)(m0 + row) * lda + kbase + (c << 3);
            cp16(sb + row * RSTR + c * 16 + A_OF, A + go, 16);
        }
#pragma unroll
        for (int i = tid; i < BR * CH; i += BD) {
            const int row = i / CH, c = i % CH;
            const int sz  = ((n0 + row) < N) ? 16 : 0;
            const long long go = (long long)(n0 + row) * ldb + kbase + (c << 3);
            cp16(sb + row * RSTR + c * 16 + B_OF, B + (sz ? go : 0), sz);
        }
    };

    float acc[4][8][4] = {};

    fill(0);
    CP_COMMIT();

    const int lrow = lane & 15;
    const int lcol = (lane >> 4) << 3;

    for (int s = 0; s < nst; s++) {
        CP_WAIT0();
        __syncthreads();
        if (s + 1 < nst) { fill(s + 1); CP_COMMIT(); }

        const uint32_t sb = smb + (uint32_t)((s & 1) * STG);
#pragma unroll
        for (int ks = 0; ks < KC / 16; ks++) {
            const int kk = ks << 4;
            uint32_t af[4][4];
#pragma unroll
            for (int mf = 0; mf < 4; mf++) {
                uint32_t ra = sb + (uint32_t)((wm * 64 + mf * 16 + lrow) * RSTR
                                              + (kk + lcol) * 2);
                ldsm_x4(af[mf][0], af[mf][1], af[mf][2], af[mf][3], ra + A_OF);
            }
#pragma unroll
            for (int nfp = 0; nfp < 4; nfp++) {
                uint32_t rb = sb + (uint32_t)((wn * 64 + nfp * 16 + lrow) * RSTR
                                              + (kk + lcol) * 2);
                uint32_t bh[4];
                ldsm_x4(bh[0], bh[1], bh[2], bh[3], rb + B_OF);
#pragma unroll
                for (int mf = 0; mf < 4; mf++) {
                    mma_f16(acc[mf][2 * nfp],     af[mf], bh[0], bh[2]);
                    mma_f16(acc[mf][2 * nfp + 1], af[mf], bh[1], bh[3]);
                }
            }
        }
    }

    const int g = lane >> 2;
    const int t = lane & 3;
#pragma unroll
    for (int mf = 0; mf < 4; mf++) {
        const int gm0 = m0 + wm * 64 + mf * 16 + g;
        const long long ro0 = (long long)gm0 * ldc;
        const long long ro1 = ro0 + 8LL * ldc;
#pragma unroll
        for (int nf = 0; nf < 8; nf++) {
            const int gn = n0 + wn * 64 + nf * 8 + t * 2;
            if (gn < N) {
                float c0 = acc[mf][nf][0] * alpha;
                float c1 = acc[mf][nf][1] * alpha;
                float c2 = acc[mf][nf][2] * alpha;
                float c3 = acc[mf][nf][3] * alpha;
                if (bias) {
                    float b0 = bias[gn], b1 = bias[gn + 1];
                    c0 += b0; c1 += b1; c2 += b0; c3 += b1;
                }
                if (RELU) {
                    c0 = fmaxf(c0, 0.0f); c1 = fmaxf(c1, 0.0f);
                    c2 = fmaxf(c2, 0.0f); c3 = fmaxf(c3, 0.0f);
                }
                if (!HOUT) {
                    if (resid) {
                        c0 += resid[ro0 + gn]; c1 += resid[ro0 + gn + 1];
                        c2 += resid[ro1 + gn]; c3 += resid[ro1 + gn + 1];
                    }
                    *(float2*)(C + ro0 + gn) = make_float2(c0, c1);
                    *(float2*)(C + ro1 + gn) = make_float2(c2, c3);
                } else {
                    *(uint32_t*)(Ch + ro0 + gn) = pk2h(c0, c1);
                    *(uint32_t*)(Ch + ro1 + gn) = pk2h(c2, c3);
                }
            }
        }
    }
}

#define SM22 (2 * (128 + 128) * 176)   // 90112  (KC=64)
#define SM12 (2 * (64 + 128) * 272)    // 104448 (KC=128)

// ---------------------------------------------------------------------------
// Host launcher (graph-capturable: kernel launches only)
// ---------------------------------------------------------------------------
extern "C" void kernel_launch(void* const* d_in, const int* in_sizes, int n_in,
                              void* d_out, int out_size) {
    const unsigned int* idw = (const unsigned int*)d_in[0];
    const float* emb  = (const float*)d_in[1];
    const float* Wq   = (const float*)d_in[2];
    const float* Wk   = (const float*)d_in[3];
    const float* Wv   = (const float*)d_in[4];
    const float* Wo   = (const float*)d_in[5];
    const float* pbq  = (const float*)d_in[6];
    const float* pbk  = (const float*)d_in[7];
    const float* pbv  = (const float*)d_in[8];
    const float* pbo  = (const float*)d_in[9];
    const float* W1   = (const float*)d_in[10];
    const float* pb1  = (const float*)d_in[11];
    const float* W2   = (const float*)d_in[12];
    const float* pb2  = (const float*)d_in[13];
    const float* ln1g = (const float*)d_in[14];
    const float* ln1b = (const float*)d_in[15];
    const float* ln2g = (const float*)d_in[16];
    const float* ln2b = (const float*)d_in[17];
    const float* lnfg = (const float*)d_in[18];
    const float* lnfb = (const float*)d_in[19];

    float *px, *pbqkv;
    hf *pn, *pqkv, *pc, *ph1;
    hf *pwqkv, *pwo, *pw1, *pw2;
    cudaGetSymbolAddress((void**)&px,    g_x);
    cudaGetSymbolAddress((void**)&pbqkv, g_bqkv);
    cudaGetSymbolAddress((void**)&pn,    g_n);
    cudaGetSymbolAddress((void**)&pqkv,  g_qkv);
    cudaGetSymbolAddress((void**)&pc,    g_c);
    cudaGetSymbolAddress((void**)&ph1,   g_h1);
    cudaGetSymbolAddress((void**)&pwqkv, g_wqkv);
    cudaGetSymbolAddress((void**)&pwo,   g_wo);
    cudaGetSymbolAddress((void**)&pw1,   g_w1);
    cudaGetSymbolAddress((void**)&pw2,   g_w2);

    cudaFuncSetAttribute(gemm1<2, 2, 64,  false, true>,
                         cudaFuncAttributeMaxDynamicSharedMemorySize, SM22);
    cudaFuncSetAttribute(gemm1<2, 2, 64,  true,  true>,
                         cudaFuncAttributeMaxDynamicSharedMemorySize, SM22);
    cudaFuncSetAttribute(gemm1<1, 2, 128, false, false>,
                         cudaFuncAttributeMaxDynamicSharedMemorySize, SM12);
    cudaFuncSetAttribute(flash_kernel,
                         cudaFuncAttributeMaxDynamicSharedMemorySize, SMEM_FLASH);

    detect_kernel<<<1, 256>>>(idw);
    embed_kernel<<<(MM * DD + 255) / 256, 256>>>(idw, emb, px);

    {
        const size_t oQKV = (size_t)3 * DD * DD;
        wtrans_kernel<<<dim3(DD / 64, DD / 64, LL), 256>>>(Wq, pwqkv, DD, DD, oQKV);
        wtrans_kernel<<<dim3(DD / 64, DD / 64, LL), 256>>>(
            Wk, pwqkv + (size_t)DD * DD, DD, DD, oQKV);
        wtrans_kernel<<<dim3(DD / 64, DD / 64, LL), 256>>>(
            Wv, pwqkv + (size_t)2 * DD * DD, DD, DD, oQKV);
        wtrans_kernel<<<dim3(DD / 64, DD / 64, LL), 256>>>(Wo, pwo, DD, DD,
                                                           (size_t)DD * DD);
        wtrans_kernel<<<dim3(DFF / 64, DD / 64, LL), 256>>>(W1, pw1, DD, DFF,
                                                            (size_t)DD * DFF);
        wtrans_kernel<<<dim3(DD / 64, DFF / 64, LL), 256>>>(W2, pw2, DFF, DD,
                                                            (size_t)DFF * DD);
        packb_kernel<<<(LL * 3 * DD + 255) / 256, 256>>>(pbq, pbk, pbv, pbqkv);
    }

    const dim3 gQKV(D3 / 128, MM / 128);         // 480
    const dim3 gN64(DD / 128, MM / 64);          // 320
    const dim3 gFF1(DFF / 128, MM / 128);        // 1024

    for (int l = 0; l < LL; l++) {
        const size_t woff4 = (size_t)l * DD * DD;
        const size_t woffQ = (size_t)l * 3 * DD * DD;
        const size_t woff1 = (size_t)l * DD * DFF;

        layernorm_kernel<true><<<MM, 160>>>(px, nullptr, pn,
                                            ln1g + l * DD, ln1b + l * DD);

        // fused qkv projection -> packed [MM, 3840] fp16
        gemm1<2, 2, 64, false, true><<<gQKV, 128, SM22>>>(
            pn, pwqkv + woffQ, nullptr, pqkv,
            pbqkv + l * D3, nullptr,
            MM, D3, DD, DD, DD, D3, 1.0f);

        // fused attention
        flash_kernel<<<144, 256, SMEM_FLASH>>>(pqkv, pc);

        // x = x + ctx @ Wo + bo   (KC=128)
        gemm1<1, 2, 128, false, false><<<gN64, 64, SM12>>>(
            pc, pwo + woff4, px, nullptr,
            pbo + l * DD, px,
            MM, DD, DD, DD, DD, DD, 1.0f);

        layernorm_kernel<true><<<MM, 160>>>(px, nullptr, pn,
                                            ln2g + l * DD, ln2b + l * DD);

        // h1 = relu(n @ W1 + b1) -> fp16
        gemm1<2, 2, 64, true, true><<<gFF1, 128, SM22>>>(
            pn, pw1 + woff1, nullptr, ph1,
            pb1 + l * DFF, nullptr,
            MM, DFF, DD, DD, DD, DFF, 1.0f);

        // x = x + h1 @ W2 + b2   (KC=128)
        gemm1<1, 2, 128, false, false><<<gN64, 64, SM12>>>(
            ph1, pw2 + woff1, px, nullptr,
            pb2 + l * DD, px,
            MM, DD, DFF, DFF, DFF, DD, 1.0f);
    }

    layernorm_kernel<false><<<MM, 160>>>(px, (float*)d_out, nullptr,
                                         lnfg, lnfb);
}

// round 16
// speedup vs baseline: 1.2064x; 1.2064x over previous
#include <cuda_runtime.h>
#include <cuda_fp16.h>
#include <cstdint>

// ---------------------------------------------------------------------------
// CTRL transformer forward, GB300 (compute_103 -> mma.sync path).
// Round 16: exact revert to round 14 (best: 2350 us). KC=64 everywhere
// (round 15's KC=128 on MW1 broke 2-CTA/SM co-residency -> regression).
// 1-term fp16 GEMMs (fp32 accum), fused qkv, balanced flash attention with
// ldmatrix.trans V path, vectorized LN/wtrans.
// ---------------------------------------------------------------------------

#define BB   2
#define SS   1024
#define DD   1280
#define HH   16
#define DHH  80
#define DFF  8192
#define LL   4
#define MM   (BB * SS)
#define D3   (3 * DD)
#define ALPHA 0.11180339887498949f

typedef __half hf;

// fp32 scratch
__device__ float g_x[MM * DD];
__device__ float g_bqkv[LL * 3 * DD];
// fp16 activations
__device__ hf g_n[MM * DD];
__device__ hf g_qkv[(size_t)MM * 3 * DD];
__device__ hf g_c[MM * DD];
__device__ hf g_h1[(size_t)MM * DFF];
// fp16 weights [N,K]
__device__ hf g_wqkv[(size_t)LL * 3 * DD * DD];
__device__ hf g_wo[LL * DD * DD];
__device__ hf g_w1[(size_t)LL * DD * DFF];
__device__ hf g_w2[(size_t)LL * DFF * DD];
__device__ int g_ids64;

// ---------------------------------------------------------------------------
__device__ __forceinline__ uint32_t smem_u32(const void* p) {
    uint32_t a;
    asm("{ .reg .u64 t; cvta.to.shared.u64 t, %1; cvt.u32.u64 %0, t; }"
        : "=r"(a) : "l"(p));
    return a;
}

__device__ __forceinline__ void ldsm_x4(uint32_t& r0, uint32_t& r1,
                                        uint32_t& r2, uint32_t& r3,
                                        uint32_t addr) {
    asm volatile("ldmatrix.sync.aligned.m8n8.x4.shared.b16 {%0,%1,%2,%3}, [%4];"
                 : "=r"(r0), "=r"(r1), "=r"(r2), "=r"(r3) : "r"(addr));
}

__device__ __forceinline__ void ldsm_x4_t(uint32_t& r0, uint32_t& r1,
                                          uint32_t& r2, uint32_t& r3,
                                          uint32_t addr) {
    asm volatile("ldmatrix.sync.aligned.m8n8.x4.trans.shared.b16 {%0,%1,%2,%3}, [%4];"
                 : "=r"(r0), "=r"(r1), "=r"(r2), "=r"(r3) : "r"(addr));
}

__device__ __forceinline__ void mma_f16(float* d, const uint32_t* a,
                                        uint32_t b0, uint32_t b1) {
    asm volatile(
        "mma.sync.aligned.m16n8k16.row.col.f32.f16.f16.f32 "
        "{%0,%1,%2,%3},{%4,%5,%6,%7},{%8,%9},{%0,%1,%2,%3};"
        : "+f"(d[0]), "+f"(d[1]), "+f"(d[2]), "+f"(d[3])
        : "r"(a[0]), "r"(a[1]), "r"(a[2]), "r"(a[3]), "r"(b0), "r"(b1));
}

__device__ __forceinline__ void cp16(uint32_t dst, const void* src, int sz) {
    asm volatile("cp.async.cg.shared.global [%0], [%1], 16, %2;"
                 :: "r"(dst), "l"(src), "r"(sz) : "memory");
}
#define CP_COMMIT() asm volatile("cp.async.commit_group;" ::: "memory")
#define CP_WAIT0()  asm volatile("cp.async.wait_group 0;" ::: "memory")
#define CP_WAIT1()  asm volatile("cp.async.wait_group 1;" ::: "memory")

__device__ __forceinline__ uint32_t pk2h(float a, float b) {
    __half2 h = __floats2half2_rn(a, b);
    return *reinterpret_cast<uint32_t*>(&h);
}

// ---------------------------------------------------------------------------
// detect + embed
// ---------------------------------------------------------------------------
__global__ void detect_kernel(const unsigned int* __restrict__ w) {
    __shared__ int any;
    if (threadIdx.x == 0) any = 0;
    __syncthreads();
    int loc = 0;
    for (int i = 2 * threadIdx.x + 1; i < 2048; i += 512)
        loc |= (w[i] != 0u);
    if (loc) atomicOr(&any, 1);
    __syncthreads();
    if (threadIdx.x == 0) g_ids64 = any ? 0 : 1;
}

__global__ void embed_kernel(const unsigned int* __restrict__ idw,
                             const float* __restrict__ emb,
                             float* __restrict__ x) {
    int idx = blockIdx.x * 256 + threadIdx.x;
    if (idx >= MM * DD) return;
    int d   = idx % DD;
    int row = idx / DD;
    int s   = row & (SS - 1);
    int id  = g_ids64 ? (int)idw[2 * row] : (int)idw[row];
    float val = emb[(long long)id * DD + d] * 35.77708763999664f;
    int m = (d < 640) ? d : d - 640;
    float rate = expf(-0.014391156831212787f * (float)m);
    float ang  = (float)s * rate;
    val += (d < 640) ? sinf(ang) : cosf(ang);
    x[idx] = val;
}

// ---------------------------------------------------------------------------
// weight convert+transpose: fp32 [K,N] -> fp16 [N,K]; 64x64 tiles
// ---------------------------------------------------------------------------
__global__ void __launch_bounds__(256)
wtrans_kernel(const float* __restrict__ W, hf* __restrict__ oh,
              int K, int N, size_t ostride) {
    W  += (size_t)blockIdx.z * K * N;
    oh += (size_t)blockIdx.z * ostride;
    __shared__ float tf[64][65];
    const int n0 = blockIdx.x * 64, k0 = blockIdx.y * 64;
    const int tx = threadIdx.x & 15;
    const int ty = threadIdx.x >> 4;
#pragma unroll
    for (int i = 0; i < 4; i++) {
        const int r = ty + 16 * i;
        float4 v = *(const float4*)(W + (long long)(k0 + r) * N + n0 + tx * 4);
        tf[r][tx * 4 + 0] = v.x;
        tf[r][tx * 4 + 1] = v.y;
        tf[r][tx * 4 + 2] = v.z;
        tf[r][tx * 4 + 3] = v.w;
    }
    __syncthreads();
#pragma unroll
    for (int i = 0; i < 4; i++) {
        const int n = ty + 16 * i;
        uint2 pk = make_uint2(
            pk2h(tf[tx * 4 + 0][n], tf[tx * 4 + 1][n]),
            pk2h(tf[tx * 4 + 2][n], tf[tx * 4 + 3][n]));
        *(uint2*)(oh + (long long)(n0 + n) * K + k0 + tx * 4) = pk;
    }
}

// pack qkv bias: [L][3840] from bq,bk,bv
__global__ void packb_kernel(const float* __restrict__ bq,
                             const float* __restrict__ bk,
                             const float* __restrict__ bv,
                             float* __restrict__ o) {
    int i = blockIdx.x * 256 + threadIdx.x;
    if (i >= LL * 3 * DD) return;
    int l = i / (3 * DD), j = i % (3 * DD);
    float v = (j < DD) ? bq[l * DD + j]
            : (j < 2 * DD) ? bk[l * DD + j - DD]
            : bv[l * DD + j - 2 * DD];
    o[i] = v;
}

// ---------------------------------------------------------------------------
// LayerNorm: 160 threads x 8 values
// ---------------------------------------------------------------------------
template <bool HOUT>
__global__ void __launch_bounds__(160)
layernorm_kernel(const float* __restrict__ x,
                 float* __restrict__ o, hf* __restrict__ oh,
                 const float* __restrict__ g, const float* __restrict__ b) {
    const int row = blockIdx.x;
    const int t   = threadIdx.x;
    const float4* xr = (const float4*)(x + (long long)row * DD);
    __shared__ float red[5];

    float4 a0 = xr[2 * t], a1 = xr[2 * t + 1];
    float v[8] = {a0.x, a0.y, a0.z, a0.w, a1.x, a1.y, a1.z, a1.w};
    float s = 0.0f;
#pragma unroll
    for (int i = 0; i < 8; i++) s += v[i];
#pragma unroll
    for (int of = 16; of; of >>= 1) s += __shfl_xor_sync(0xffffffffu, s, of);
    if ((t & 31) == 0) red[t >> 5] = s;
    __syncthreads();
    float mu = (red[0] + red[1] + red[2] + red[3] + red[4]) * (1.0f / 1280.0f);
    __syncthreads();
    float q = 0.0f;
#pragma unroll
    for (int i = 0; i < 8; i++) { float dv = v[i] - mu; q += dv * dv; }
#pragma unroll
    for (int of = 16; of; of >>= 1) q += __shfl_xor_sync(0xffffffffu, q, of);
    if ((t & 31) == 0) red[t >> 5] = q;
    __syncthreads();
    float var = (red[0] + red[1] + red[2] + red[3] + red[4]) * (1.0f / 1280.0f);
    float rstd = rsqrtf(var + 1e-6f);

    const float4* gp = (const float4*)(g + 8 * t);
    const float4* bp = (const float4*)(b + 8 * t);
    float4 g0 = gp[0], g1 = gp[1], b0 = bp[0], b1 = bp[1];
    float gg[8] = {g0.x, g0.y, g0.z, g0.w, g1.x, g1.y, g1.z, g1.w};
    float bb[8] = {b0.x, b0.y, b0.z, b0.w, b1.x, b1.y, b1.z, b1.w};

    float y[8];
#pragma unroll
    for (int i = 0; i < 8; i++) y[i] = (v[i] - mu) * rstd * gg[i] + bb[i];

    if (HOUT) {
        uint4 pk = make_uint4(pk2h(y[0], y[1]), pk2h(y[2], y[3]),
                              pk2h(y[4], y[5]), pk2h(y[6], y[7]));
        ((uint4*)(oh + (long long)row * DD))[t] = pk;
    } else {
        float4* op = (float4*)(o + (long long)row * DD);
        op[2 * t]     = make_float4(y[0], y[1], y[2], y[3]);
        op[2 * t + 1] = make_float4(y[4], y[5], y[6], y[7]);
    }
}

// ---------------------------------------------------------------------------
// Flash attention: 144 balanced CTAs, v via ldmatrix.trans from packed qkv.
// ---------------------------------------------------------------------------
#define FQ_OF 0
#define FK_OF 22528
#define FV_OF 67584
#define SMEM_FLASH 112640

__global__ void __launch_bounds__(256, 1)
flash_kernel(const hf* __restrict__ qkv, hf* __restrict__ ctx) {
    const int z = blockIdx.x;
    int np, qts[2], bhs[2];
    if (z < 32)       { np = 1; bhs[0] = z; qts[0] = 7; bhs[1] = 0; qts[1] = 0; }
    else if (z < 128) { int gi = z >> 5; int bh = z & 31;
                        np = 2; bhs[0] = bhs[1] = bh;
                        qts[0] = 7 - gi; qts[1] = gi - 1; }
    else              { int i = z - 128;
                        np = 2; bhs[0] = 2 * i; bhs[1] = 2 * i + 1;
                        qts[0] = qts[1] = 3; }

    extern __shared__ char sm[];
    const uint32_t smb = smem_u32(sm);

    const int tid = threadIdx.x;
    const int wid = tid >> 5, lane = tid & 31;
    const int g = lane >> 2, t = lane & 3;
    const int lrow = lane & 15, lcol = (lane >> 4) << 3;
    const int wr0 = wid * 16;
    const int vrow = ((lane >> 3) & 1) * 8 + (lane & 7);
    const int vcol = (lane >> 4) << 3;

    for (int pass = 0; pass < np; pass++) {
        const int qt = qts[pass];
        const int bh = bhs[pass];
        const int zb = bh >> 4, zh = bh & 15;

        const hf* kbase = qkv + (long long)zb * SS * D3 + DD + zh * DHH;
        const hf* vbase = kbase + DD;

        auto fillKV = [&](int j) {
            const uint32_t kb = smb + FK_OF + (j & 1) * 22528;
            const uint32_t vb = smb + FV_OF + (j & 1) * 22528;
            const long long ro = (long long)(j * 128) * D3;
            for (int i = tid; i < 1280; i += 256) {
                int r = i / 10, c = i % 10;
                const long long go = ro + (long long)r * D3 + c * 8;
                cp16(kb + r * 176 + c * 16, kbase + go, 16);
                cp16(vb + r * 176 + c * 16, vbase + go, 16);
            }
        };

        const long long qtok0 = (long long)zb * SS + qt * 128;
        const hf* qbase = qkv + qtok0 * D3 + zh * DHH;
        const int qrow = qt * 128 + wr0 + g;

        for (int i = tid; i < 1280; i += 256) {
            int r = i / 10, c = i % 10;
            cp16(smb + FQ_OF + r * 176 + c * 16,
                 qbase + (long long)r * D3 + c * 8, 16);
        }
        fillKV(0); CP_COMMIT();
        if (qt >= 1) { fillKV(1); CP_COMMIT(); }

        float o[10][4] = {};
        float mx0 = -3.4e38f, mx1 = -3.4e38f, sum0 = 0.0f, sum1 = 0.0f;

        for (int j = 0; j <= qt; j++) {
            if (j + 1 <= qt) CP_WAIT1(); else CP_WAIT0();
            __syncthreads();

            const uint32_t kb = smb + FK_OF + (j & 1) * 22528;
            const uint32_t vb = smb + FV_OF + (j & 1) * 22528;

            float s[16][4] = {};
#pragma unroll
            for (int kc = 0; kc < 5; kc++) {
                uint32_t a[4];
                ldsm_x4(a[0], a[1], a[2], a[3],
                        smb + FQ_OF + (wr0 + lrow) * 176 + (kc * 16 + lcol) * 2);
#pragma unroll
                for (int nfp = 0; nfp < 8; nfp++) {
                    uint32_t b[4];
                    ldsm_x4(b[0], b[1], b[2], b[3],
                            kb + (nfp * 16 + lrow) * 176 + (kc * 16 + lcol) * 2);
                    mma_f16(s[2 * nfp],     a, b[0], b[2]);
                    mma_f16(s[2 * nfp + 1], a, b[1], b[3]);
                }
            }

            const bool diag = (j == qt);
            const int kb0 = j * 128;
            float tm0 = -3.4e38f, tm1 = -3.4e38f;
#pragma unroll
            for (int nf = 0; nf < 16; nf++) {
                const int col = kb0 + nf * 8 + 2 * t;
#pragma unroll
                for (int e = 0; e < 2; e++) {
                    float v0 = s[nf][e]     * ALPHA;
                    float v1 = s[nf][e + 2] * ALPHA;
                    if (diag) {
                        if (col + e > qrow)     v0 = -3.4e38f;
                        if (col + e > qrow + 8) v1 = -3.4e38f;
                    }
                    s[nf][e] = v0; s[nf][e + 2] = v1;
                    tm0 = fmaxf(tm0, v0); tm1 = fmaxf(tm1, v1);
                }
            }
            tm0 = fmaxf(tm0, __shfl_xor_sync(0xffffffffu, tm0, 1));
            tm0 = fmaxf(tm0, __shfl_xor_sync(0xffffffffu, tm0, 2));
            tm1 = fmaxf(tm1, __shfl_xor_sync(0xffffffffu, tm1, 1));
            tm1 = fmaxf(tm1, __shfl_xor_sync(0xffffffffu, tm1, 2));

            const float nmx0 = fmaxf(mx0, tm0), nmx1 = fmaxf(mx1, tm1);
            const float sc0 = expf(mx0 - nmx0), sc1 = expf(mx1 - nmx1);
            mx0 = nmx0; mx1 = nmx1;

            uint32_t pA[8][4];
            float ts0 = 0.0f, ts1 = 0.0f;
#pragma unroll
            for (int nf = 0; nf < 16; nf++) {
                float e0 = expf(s[nf][0] - mx0);
                float e1 = expf(s[nf][1] - mx0);
                float e2 = expf(s[nf][2] - mx1);
                float e3 = expf(s[nf][3] - mx1);
                ts0 += e0 + e1; ts1 += e2 + e3;
                const int kc2 = nf >> 1, hi = nf & 1;
                pA[kc2][hi * 2]     = pk2h(e0, e1);
                pA[kc2][hi * 2 + 1] = pk2h(e2, e3);
            }
            ts0 += __shfl_xor_sync(0xffffffffu, ts0, 1);
            ts0 += __shfl_xor_sync(0xffffffffu, ts0, 2);
            ts1 += __shfl_xor_sync(0xffffffffu, ts1, 1);
            ts1 += __shfl_xor_sync(0xffffffffu, ts1, 2);
            sum0 = sum0 * sc0 + ts0;
            sum1 = sum1 * sc1 + ts1;

#pragma unroll
            for (int nf = 0; nf < 10; nf++) {
                o[nf][0] *= sc0; o[nf][1] *= sc0;
                o[nf][2] *= sc1; o[nf][3] *= sc1;
            }
#pragma unroll
            for (int nfp2 = 0; nfp2 < 5; nfp2++) {
#pragma unroll
                for (int kc2 = 0; kc2 < 8; kc2++) {
                    uint32_t b[4];
                    ldsm_x4_t(b[0], b[1], b[2], b[3],
                              vb + (kc2 * 16 + vrow) * 176
                                 + (nfp2 * 16 + vcol) * 2);
                    mma_f16(o[2 * nfp2],     pA[kc2], b[0], b[1]);
                    mma_f16(o[2 * nfp2 + 1], pA[kc2], b[2], b[3]);
                }
            }

            __syncthreads();
            if (j + 2 <= qt) { fillKV(j + 2); CP_COMMIT(); }
        }

        const float inv0 = 1.0f / sum0, inv1 = 1.0f / sum1;
        const long long r0 = (qtok0 + wr0 + g) * DD + zh * DHH;
        const long long r1 = r0 + 8LL * DD;
#pragma unroll
        for (int nf = 0; nf < 10; nf++) {
            const int d = nf * 8 + 2 * t;
            *(uint32_t*)(ctx + r0 + d) = pk2h(o[nf][0] * inv0, o[nf][1] * inv0);
            *(uint32_t*)(ctx + r1 + d) = pk2h(o[nf][2] * inv1, o[nf][3] * inv1);
        }
    }
}

// ---------------------------------------------------------------------------
// fp16 GEMM, K-chunk 64: C = alpha*A@B^T [+bias][relu][+resid].
// Row stride 176B (128B data + 48 pad): conflict-free ldsm.
// ---------------------------------------------------------------------------
template <int MW, int NW, bool RELU, bool HOUT>
__global__ void __launch_bounds__(MW * NW * 32)
gemm1(const hf* __restrict__ A, const hf* __restrict__ B,
      float* __restrict__ C, hf* __restrict__ Ch,
      const float* __restrict__ bias, const float* __restrict__ resid,
      int M, int N, int K, int lda, int ldb, int ldc, float alpha) {
    constexpr int AR  = 64 * MW;
    constexpr int BR  = 64 * NW;
    constexpr int BD  = MW * NW * 32;
    constexpr int A_OF = 0;
    constexpr int B_OF = AR * 176;
    constexpr int STG  = (AR + BR) * 176;

    const int m0 = blockIdx.y * AR;
    const int n0 = blockIdx.x * BR;

    extern __shared__ char sm[];
    const uint32_t smb = smem_u32(sm);

    const int tid  = threadIdx.x;
    const int wid  = tid >> 5;
    const int lane = tid & 31;
    const int wm   = wid / NW;
    const int wn   = wid % NW;

    const int nst = (K + 63) >> 6;

    auto fill = [&](int s) {
        const uint32_t sb = smb + (uint32_t)((s & 1) * STG);
        const int kbase = s << 6;
#pragma unroll
        for (int i = tid; i < AR * 8; i += BD) {
            const int row = i >> 3, c = i & 7;
            const long long go = (long long)(m0 + row) * lda + kbase + (c << 3);
            cp16(sb + row * 176 + c * 16 + A_OF, A + go, 16);
        }
#pragma unroll
        for (int i = tid; i < BR * 8; i += BD) {
            const int row = i >> 3, c = i & 7;
            const int sz  = ((n0 + row) < N) ? 16 : 0;
            const long long go = (long long)(n0 + row) * ldb + kbase + (c << 3);
            cp16(sb + row * 176 + c * 16 + B_OF, B + (sz ? go : 0), sz);
        }
    };

    float acc[4][8][4] = {};

    fill(0);
    CP_COMMIT();

    const int lrow = lane & 15;
    const int lcol = (lane >> 4) << 3;

    for (int s = 0; s < nst; s++) {
        CP_WAIT0();
        __syncthreads();
        if (s + 1 < nst) { fill(s + 1); CP_COMMIT(); }

        const uint32_t sb = smb + (uint32_t)((s & 1) * STG);
#pragma unroll
        for (int ks = 0; ks < 4; ks++) {
            const int kk = ks << 4;
            uint32_t af[4][4];
#pragma unroll
            for (int mf = 0; mf < 4; mf++) {
                uint32_t ra = sb + (uint32_t)((wm * 64 + mf * 16 + lrow) * 176
                                              + (kk + lcol) * 2);
                ldsm_x4(af[mf][0], af[mf][1], af[mf][2], af[mf][3], ra + A_OF);
            }
#pragma unroll
            for (int nfp = 0; nfp < 4; nfp++) {
                uint32_t rb = sb + (uint32_t)((wn * 64 + nfp * 16 + lrow) * 176
                                              + (kk + lcol) * 2);
                uint32_t bh[4];
                ldsm_x4(bh[0], bh[1], bh[2], bh[3], rb + B_OF);
#pragma unroll
                for (int mf = 0; mf < 4; mf++) {
                    mma_f16(acc[mf][2 * nfp],     af[mf], bh[0], bh[2]);
                    mma_f16(acc[mf][2 * nfp + 1], af[mf], bh[1], bh[3]);
                }
            }
        }
    }

    const int g = lane >> 2;
    const int t = lane & 3;
#pragma unroll
    for (int mf = 0; mf < 4; mf++) {
        const int gm0 = m0 + wm * 64 + mf * 16 + g;
        const long long ro0 = (long long)gm0 * ldc;
        const long long ro1 = ro0 + 8LL * ldc;
#pragma unroll
        for (int nf = 0; nf < 8; nf++) {
            const int gn = n0 + wn * 64 + nf * 8 + t * 2;
            if (gn < N) {
                float c0 = acc[mf][nf][0] * alpha;
                float c1 = acc[mf][nf][1] * alpha;
                float c2 = acc[mf][nf][2] * alpha;
                float c3 = acc[mf][nf][3] * alpha;
                if (bias) {
                    float b0 = bias[gn], b1 = bias[gn + 1];
                    c0 += b0; c1 += b1; c2 += b0; c3 += b1;
                }
                if (RELU) {
                    c0 = fmaxf(c0, 0.0f); c1 = fmaxf(c1, 0.0f);
                    c2 = fmaxf(c2, 0.0f); c3 = fmaxf(c3, 0.0f);
                }
                if (!HOUT) {
                    if (resid) {
                        c0 += resid[ro0 + gn]; c1 += resid[ro0 + gn + 1];
                        c2 += resid[ro1 + gn]; c3 += resid[ro1 + gn + 1];
                    }
                    *(float2*)(C + ro0 + gn) = make_float2(c0, c1);
                    *(float2*)(C + ro1 + gn) = make_float2(c2, c3);
                } else {
                    *(uint32_t*)(Ch + ro0 + gn) = pk2h(c0, c1);
                    *(uint32_t*)(Ch + ro1 + gn) = pk2h(c2, c3);
                }
            }
        }
    }
}

#define SM22 (2 * (128 + 128) * 176)   // 90112
#define SM12 (2 * (64 + 128) * 176)    // 67584

// ---------------------------------------------------------------------------
// Host launcher (graph-capturable: kernel launches only)
// ---------------------------------------------------------------------------
extern "C" void kernel_launch(void* const* d_in, const int* in_sizes, int n_in,
                              void* d_out, int out_size) {
    const unsigned int* idw = (const unsigned int*)d_in[0];
    const float* emb  = (const float*)d_in[1];
    const float* Wq   = (const float*)d_in[2];
    const float* Wk   = (const float*)d_in[3];
    const float* Wv   = (const float*)d_in[4];
    const float* Wo   = (const float*)d_in[5];
    const float* pbq  = (const float*)d_in[6];
    const float* pbk  = (const float*)d_in[7];
    const float* pbv  = (const float*)d_in[8];
    const float* pbo  = (const float*)d_in[9];
    const float* W1   = (const float*)d_in[10];
    const float* pb1  = (const float*)d_in[11];
    const float* W2   = (const float*)d_in[12];
    const float* pb2  = (const float*)d_in[13];
    const float* ln1g = (const float*)d_in[14];
    const float* ln1b = (const float*)d_in[15];
    const float* ln2g = (const float*)d_in[16];
    const float* ln2b = (const float*)d_in[17];
    const float* lnfg = (const float*)d_in[18];
    const float* lnfb = (const float*)d_in[19];

    float *px, *pbqkv;
    hf *pn, *pqkv, *pc, *ph1;
    hf *pwqkv, *pwo, *pw1, *pw2;
    cudaGetSymbolAddress((void**)&px,    g_x);
    cudaGetSymbolAddress((void**)&pbqkv, g_bqkv);
    cudaGetSymbolAddress((void**)&pn,    g_n);
    cudaGetSymbolAddress((void**)&pqkv,  g_qkv);
    cudaGetSymbolAddress((void**)&pc,    g_c);
    cudaGetSymbolAddress((void**)&ph1,   g_h1);
    cudaGetSymbolAddress((void**)&pwqkv, g_wqkv);
    cudaGetSymbolAddress((void**)&pwo,   g_wo);
    cudaGetSymbolAddress((void**)&pw1,   g_w1);
    cudaGetSymbolAddress((void**)&pw2,   g_w2);

    cudaFuncSetAttribute(gemm1<2, 2, false, true>,
                         cudaFuncAttributeMaxDynamicSharedMemorySize, SM22);
    cudaFuncSetAttribute(gemm1<2, 2, true,  true>,
                         cudaFuncAttributeMaxDynamicSharedMemorySize, SM22);
    cudaFuncSetAttribute(gemm1<1, 2, false, false>,
                         cudaFuncAttributeMaxDynamicSharedMemorySize, SM12);
    cudaFuncSetAttribute(flash_kernel,
                         cudaFuncAttributeMaxDynamicSharedMemorySize, SMEM_FLASH);

    detect_kernel<<<1, 256>>>(idw);
    embed_kernel<<<(MM * DD + 255) / 256, 256>>>(idw, emb, px);

    {
        const size_t oQKV = (size_t)3 * DD * DD;
        wtrans_kernel<<<dim3(DD / 64, DD / 64, LL), 256>>>(Wq, pwqkv, DD, DD, oQKV);
        wtrans_kernel<<<dim3(DD / 64, DD / 64, LL), 256>>>(
            Wk, pwqkv + (size_t)DD * DD, DD, DD, oQKV);
        wtrans_kernel<<<dim3(DD / 64, DD / 64, LL), 256>>>(
            Wv, pwqkv + (size_t)2 * DD * DD, DD, DD, oQKV);
        wtrans_kernel<<<dim3(DD / 64, DD / 64, LL), 256>>>(Wo, pwo, DD, DD,
                                                           (size_t)DD * DD);
        wtrans_kernel<<<dim3(DFF / 64, DD / 64, LL), 256>>>(W1, pw1, DD, DFF,
                                                            (size_t)DD * DFF);
        wtrans_kernel<<<dim3(DD / 64, DFF / 64, LL), 256>>>(W2, pw2, DFF, DD,
                                                            (size_t)DFF * DD);
        packb_kernel<<<(LL * 3 * DD + 255) / 256, 256>>>(pbq, pbk, pbv, pbqkv);
    }

    const dim3 gQKV(D3 / 128, MM / 128);         // 480
    const dim3 gN64(DD / 128, MM / 64);          // 320
    const dim3 gFF1(DFF / 128, MM / 128);        // 1024

    for (int l = 0; l < LL; l++) {
        const size_t woff4 = (size_t)l * DD * DD;
        const size_t woffQ = (size_t)l * 3 * DD * DD;
        const size_t woff1 = (size_t)l * DD * DFF;

        layernorm_kernel<true><<<MM, 160>>>(px, nullptr, pn,
                                            ln1g + l * DD, ln1b + l * DD);

        // fused qkv projection -> packed [MM, 3840] fp16
        gemm1<2, 2, false, true><<<gQKV, 128, SM22>>>(
            pn, pwqkv + woffQ, nullptr, pqkv,
            pbqkv + l * D3, nullptr,
            MM, D3, DD, DD, DD, D3, 1.0f);

        // fused attention
        flash_kernel<<<144, 256, SMEM_FLASH>>>(pqkv, pc);

        // x = x + ctx @ Wo + bo
        gemm1<1, 2, false, false><<<gN64, 64, SM12>>>(
            pc, pwo + woff4, px, nullptr,
            pbo + l * DD, px,
            MM, DD, DD, DD, DD, DD, 1.0f);

        layernorm_kernel<true><<<MM, 160>>>(px, nullptr, pn,
                                            ln2g + l * DD, ln2b + l * DD);

        // h1 = relu(n @ W1 + b1) -> fp16
        gemm1<2, 2, true, true><<<gFF1, 128, SM22>>>(
            pn, pw1 + woff1, nullptr, ph1,
            pb1 + l * DFF, nullptr,
            MM, DFF, DD, DD, DD, DFF, 1.0f);

        // x = x + h1 @ W2 + b2
        gemm1<1, 2, false, false><<<gN64, 64, SM12>>>(
            ph1, pw2 + woff1, px, nullptr,
            pb2 + l * DD, px,
            MM, DD, DFF, DFF, DFF, DD, 1.0f);
    }

    layernorm_kernel<false><<<MM, 160>>>(px, (float*)d_out, nullptr,
                                         lnfg, lnfb);
}

// round 17
// speedup vs baseline: 1.2090x; 1.0022x over previous
#include <cuda_runtime.h>
#include <cuda_fp16.h>
#include <cstdint>

// ---------------------------------------------------------------------------
// CTRL transformer forward, GB300 (compute_103 -> mma.sync path).
// Round 17: round 16 (best, 2341us) + merged DDxDD weight transposes
// (Wq/Wk/Wv/Wo x 4 layers in ONE launch; bit-identical output).
// 1-term fp16 GEMMs (fp32 accum, KC=64), fused qkv, balanced flash attention
// (ldmatrix.trans V), vectorized LN.
// ---------------------------------------------------------------------------

#define BB   2
#define SS   1024
#define DD   1280
#define HH   16
#define DHH  80
#define DFF  8192
#define LL   4
#define MM   (BB * SS)
#define D3   (3 * DD)
#define ALPHA 0.11180339887498949f

typedef __half hf;

// fp32 scratch
__device__ float g_x[MM * DD];
__device__ float g_bqkv[LL * 3 * DD];
// fp16 activations
__device__ hf g_n[MM * DD];
__device__ hf g_qkv[(size_t)MM * 3 * DD];
__device__ hf g_c[MM * DD];
__device__ hf g_h1[(size_t)MM * DFF];
// fp16 weights [N,K]
__device__ hf g_wqkv[(size_t)LL * 3 * DD * DD];
__device__ hf g_wo[LL * DD * DD];
__device__ hf g_w1[(size_t)LL * DD * DFF];
__device__ hf g_w2[(size_t)LL * DFF * DD];
__device__ int g_ids64;

// ---------------------------------------------------------------------------
__device__ __forceinline__ uint32_t smem_u32(const void* p) {
    uint32_t a;
    asm("{ .reg .u64 t; cvta.to.shared.u64 t, %1; cvt.u32.u64 %0, t; }"
        : "=r"(a) : "l"(p));
    return a;
}

__device__ __forceinline__ void ldsm_x4(uint32_t& r0, uint32_t& r1,
                                        uint32_t& r2, uint32_t& r3,
                                        uint32_t addr) {
    asm volatile("ldmatrix.sync.aligned.m8n8.x4.shared.b16 {%0,%1,%2,%3}, [%4];"
                 : "=r"(r0), "=r"(r1), "=r"(r2), "=r"(r3) : "r"(addr));
}

__device__ __forceinline__ void ldsm_x4_t(uint32_t& r0, uint32_t& r1,
                                          uint32_t& r2, uint32_t& r3,
                                          uint32_t addr) {
    asm volatile("ldmatrix.sync.aligned.m8n8.x4.trans.shared.b16 {%0,%1,%2,%3}, [%4];"
                 : "=r"(r0), "=r"(r1), "=r"(r2), "=r"(r3) : "r"(addr));
}

__device__ __forceinline__ void mma_f16(float* d, const uint32_t* a,
                                        uint32_t b0, uint32_t b1) {
    asm volatile(
        "mma.sync.aligned.m16n8k16.row.col.f32.f16.f16.f32 "
        "{%0,%1,%2,%3},{%4,%5,%6,%7},{%8,%9},{%0,%1,%2,%3};"
        : "+f"(d[0]), "+f"(d[1]), "+f"(d[2]), "+f"(d[3])
        : "r"(a[0]), "r"(a[1]), "r"(a[2]), "r"(a[3]), "r"(b0), "r"(b1));
}

__device__ __forceinline__ void cp16(uint32_t dst, const void* src, int sz) {
    asm volatile("cp.async.cg.shared.global [%0], [%1], 16, %2;"
                 :: "r"(dst), "l"(src), "r"(sz) : "memory");
}
#define CP_COMMIT() asm volatile("cp.async.commit_group;" ::: "memory")
#define CP_WAIT0()  asm volatile("cp.async.wait_group 0;" ::: "memory")
#define CP_WAIT1()  asm volatile("cp.async.wait_group 1;" ::: "memory")

__device__ __forceinline__ uint32_t pk2h(float a, float b) {
    __half2 h = __floats2half2_rn(a, b);
    return *reinterpret_cast<uint32_t*>(&h);
}

// ---------------------------------------------------------------------------
// detect + embed
// ---------------------------------------------------------------------------
__global__ void detect_kernel(const unsigned int* __restrict__ w) {
    __shared__ int any;
    if (threadIdx.x == 0) any = 0;
    __syncthreads();
    int loc = 0;
    for (int i = 2 * threadIdx.x + 1; i < 2048; i += 512)
        loc |= (w[i] != 0u);
    if (loc) atomicOr(&any, 1);
    __syncthreads();
    if (threadIdx.x == 0) g_ids64 = any ? 0 : 1;
}

__global__ void embed_kernel(const unsigned int* __restrict__ idw,
                             const float* __restrict__ emb,
                             float* __restrict__ x) {
    int idx = blockIdx.x * 256 + threadIdx.x;
    if (idx >= MM * DD) return;
    int d   = idx % DD;
    int row = idx / DD;
    int s   = row & (SS - 1);
    int id  = g_ids64 ? (int)idw[2 * row] : (int)idw[row];
    float val = emb[(long long)id * DD + d] * 35.77708763999664f;
    int m = (d < 640) ? d : d - 640;
    float rate = expf(-0.014391156831212787f * (float)m);
    float ang  = (float)s * rate;
    val += (d < 640) ? sinf(ang) : cosf(ang);
    x[idx] = val;
}

// ---------------------------------------------------------------------------
// weight convert+transpose: fp32 [K,N] -> fp16 [N,K]; 64x64 tiles
// ---------------------------------------------------------------------------
__device__ __forceinline__ void wtrans_tile(const float* __restrict__ W,
                                            hf* __restrict__ oh,
                                            int K, int N,
                                            float (*tf)[65]) {
    const int n0 = blockIdx.x * 64, k0 = blockIdx.y * 64;
    const int tx = threadIdx.x & 15;
    const int ty = threadIdx.x >> 4;
#pragma unroll
    for (int i = 0; i < 4; i++) {
        const int r = ty + 16 * i;
        float4 v = *(const float4*)(W + (long long)(k0 + r) * N + n0 + tx * 4);
        tf[r][tx * 4 + 0] = v.x;
        tf[r][tx * 4 + 1] = v.y;
        tf[r][tx * 4 + 2] = v.z;
        tf[r][tx * 4 + 3] = v.w;
    }
    __syncthreads();
#pragma unroll
    for (int i = 0; i < 4; i++) {
        const int n = ty + 16 * i;
        uint2 pk = make_uint2(
            pk2h(tf[tx * 4 + 0][n], tf[tx * 4 + 1][n]),
            pk2h(tf[tx * 4 + 2][n], tf[tx * 4 + 3][n]));
        *(uint2*)(oh + (long long)(n0 + n) * K + k0 + tx * 4) = pk;
    }
}

// general single-matrix version (W1, W2)
__global__ void __launch_bounds__(256)
wtrans_kernel(const float* __restrict__ W, hf* __restrict__ oh,
              int K, int N, size_t ostride) {
    __shared__ float tf[64][65];
    wtrans_tile(W + (size_t)blockIdx.z * K * N,
                oh + (size_t)blockIdx.z * ostride, K, N, tf);
}

// merged DDxDD version: z = layer*4 + {0:Wq,1:Wk,2:Wv,3:Wo}
__global__ void __launch_bounds__(256)
wtrans4_kernel(const float* __restrict__ Wq, const float* __restrict__ Wk,
               const float* __restrict__ Wv, const float* __restrict__ Wo,
               hf* __restrict__ oqkv, hf* __restrict__ oo) {
    __shared__ float tf[64][65];
    const int l = blockIdx.z >> 2, m = blockIdx.z & 3;
    const size_t woff = (size_t)l * DD * DD;
    const float* W = (m == 0) ? Wq + woff
                   : (m == 1) ? Wk + woff
                   : (m == 2) ? Wv + woff : Wo + woff;
    hf* oh = (m < 3) ? oqkv + (size_t)l * 3 * DD * DD + (size_t)m * DD * DD
                     : oo + woff;
    wtrans_tile(W, oh, DD, DD, tf);
}

// pack qkv bias: [L][3840] from bq,bk,bv
__global__ void packb_kernel(const float* __restrict__ bq,
                             const float* __restrict__ bk,
                             const float* __restrict__ bv,
                             float* __restrict__ o) {
    int i = blockIdx.x * 256 + threadIdx.x;
    if (i >= LL * 3 * DD) return;
    int l = i / (3 * DD), j = i % (3 * DD);
    float v = (j < DD) ? bq[l * DD + j]
            : (j < 2 * DD) ? bk[l * DD + j - DD]
            : bv[l * DD + j - 2 * DD];
    o[i] = v;
}

// ---------------------------------------------------------------------------
// LayerNorm: 160 threads x 8 values
// ---------------------------------------------------------------------------
template <bool HOUT>
__global__ void __launch_bounds__(160)
layernorm_kernel(const float* __restrict__ x,
                 float* __restrict__ o, hf* __restrict__ oh,
                 const float* __restrict__ g, const float* __restrict__ b) {
    const int row = blockIdx.x;
    const int t   = threadIdx.x;
    const float4* xr = (const float4*)(x + (long long)row * DD);
    __shared__ float red[5];

    float4 a0 = xr[2 * t], a1 = xr[2 * t + 1];
    float v[8] = {a0.x, a0.y, a0.z, a0.w, a1.x, a1.y, a1.z, a1.w};
    float s = 0.0f;
#pragma unroll
    for (int i = 0; i < 8; i++) s += v[i];
#pragma unroll
    for (int of = 16; of; of >>= 1) s += __shfl_xor_sync(0xffffffffu, s, of);
    if ((t & 31) == 0) red[t >> 5] = s;
    __syncthreads();
    float mu = (red[0] + red[1] + red[2] + red[3] + red[4]) * (1.0f / 1280.0f);
    __syncthreads();
    float q = 0.0f;
#pragma unroll
    for (int i = 0; i < 8; i++) { float dv = v[i] - mu; q += dv * dv; }
#pragma unroll
    for (int of = 16; of; of >>= 1) q += __shfl_xor_sync(0xffffffffu, q, of);
    if ((t & 31) == 0) red[t >> 5] = q;
    __syncthreads();
    float var = (red[0] + red[1] + red[2] + red[3] + red[4]) * (1.0f / 1280.0f);
    float rstd = rsqrtf(var + 1e-6f);

    const float4* gp = (const float4*)(g + 8 * t);
    const float4* bp = (const float4*)(b + 8 * t);
    float4 g0 = gp[0], g1 = gp[1], b0 = bp[0], b1 = bp[1];
    float gg[8] = {g0.x, g0.y, g0.z, g0.w, g1.x, g1.y, g1.z, g1.w};
    float bb[8] = {b0.x, b0.y, b0.z, b0.w, b1.x, b1.y, b1.z, b1.w};

    float y[8];
#pragma unroll
    for (int i = 0; i < 8; i++) y[i] = (v[i] - mu) * rstd * gg[i] + bb[i];

    if (HOUT) {
        uint4 pk = make_uint4(pk2h(y[0], y[1]), pk2h(y[2], y[3]),
                              pk2h(y[4], y[5]), pk2h(y[6], y[7]));
        ((uint4*)(oh + (long long)row * DD))[t] = pk;
    } else {
        float4* op = (float4*)(o + (long long)row * DD);
        op[2 * t]     = make_float4(y[0], y[1], y[2], y[3]);
        op[2 * t + 1] = make_float4(y[4], y[5], y[6], y[7]);
    }
}

// ---------------------------------------------------------------------------
// Flash attention: 144 balanced CTAs, v via ldmatrix.trans from packed qkv.
// ---------------------------------------------------------------------------
#define FQ_OF 0
#define FK_OF 22528
#define FV_OF 67584
#define SMEM_FLASH 112640

__global__ void __launch_bounds__(256, 1)
flash_kernel(const hf* __restrict__ qkv, hf* __restrict__ ctx) {
    const int z = blockIdx.x;
    int np, qts[2], bhs[2];
    if (z < 32)       { np = 1; bhs[0] = z; qts[0] = 7; bhs[1] = 0; qts[1] = 0; }
    else if (z < 128) { int gi = z >> 5; int bh = z & 31;
                        np = 2; bhs[0] = bhs[1] = bh;
                        qts[0] = 7 - gi; qts[1] = gi - 1; }
    else              { int i = z - 128;
                        np = 2; bhs[0] = 2 * i; bhs[1] = 2 * i + 1;
                        qts[0] = qts[1] = 3; }

    extern __shared__ char sm[];
    const uint32_t smb = smem_u32(sm);

    const int tid = threadIdx.x;
    const int wid = tid >> 5, lane = tid & 31;
    const int g = lane >> 2, t = lane & 3;
    const int lrow = lane & 15, lcol = (lane >> 4) << 3;
    const int wr0 = wid * 16;
    const int vrow = ((lane >> 3) & 1) * 8 + (lane & 7);
    const int vcol = (lane >> 4) << 3;

    for (int pass = 0; pass < np; pass++) {
        const int qt = qts[pass];
        const int bh = bhs[pass];
        const int zb = bh >> 4, zh = bh & 15;

        const hf* kbase = qkv + (long long)zb * SS * D3 + DD + zh * DHH;
        const hf* vbase = kbase + DD;

        auto fillKV = [&](int j) {
            const uint32_t kb = smb + FK_OF + (j & 1) * 22528;
            const uint32_t vb = smb + FV_OF + (j & 1) * 22528;
            const long long ro = (long long)(j * 128) * D3;
            for (int i = tid; i < 1280; i += 256) {
                int r = i / 10, c = i % 10;
                const long long go = ro + (long long)r * D3 + c * 8;
                cp16(kb + r * 176 + c * 16, kbase + go, 16);
                cp16(vb + r * 176 + c * 16, vbase + go, 16);
            }
        };

        const long long qtok0 = (long long)zb * SS + qt * 128;
        const hf* qbase = qkv + qtok0 * D3 + zh * DHH;
        const int qrow = qt * 128 + wr0 + g;

        for (int i = tid; i < 1280; i += 256) {
            int r = i / 10, c = i % 10;
            cp16(smb + FQ_OF + r * 176 + c * 16,
                 qbase + (long long)r * D3 + c * 8, 16);
        }
        fillKV(0); CP_COMMIT();
        if (qt >= 1) { fillKV(1); CP_COMMIT(); }

        float o[10][4] = {};
        float mx0 = -3.4e38f, mx1 = -3.4e38f, sum0 = 0.0f, sum1 = 0.0f;

        for (int j = 0; j <= qt; j++) {
            if (j + 1 <= qt) CP_WAIT1(); else CP_WAIT0();
            __syncthreads();

            const uint32_t kb = smb + FK_OF + (j & 1) * 22528;
            const uint32_t vb = smb + FV_OF + (j & 1) * 22528;

            float s[16][4] = {};
#pragma unroll
            for (int kc = 0; kc < 5; kc++) {
                uint32_t a[4];
                ldsm_x4(a[0], a[1], a[2], a[3],
                        smb + FQ_OF + (wr0 + lrow) * 176 + (kc * 16 + lcol) * 2);
#pragma unroll
                for (int nfp = 0; nfp < 8; nfp++) {
                    uint32_t b[4];
                    ldsm_x4(b[0], b[1], b[2], b[3],
                            kb + (nfp * 16 + lrow) * 176 + (kc * 16 + lcol) * 2);
                    mma_f16(s[2 * nfp],     a, b[0], b[2]);
                    mma_f16(s[2 * nfp + 1], a, b[1], b[3]);
                }
            }

            const bool diag = (j == qt);
            const int kb0 = j * 128;
            float tm0 = -3.4e38f, tm1 = -3.4e38f;
#pragma unroll
            for (int nf = 0; nf < 16; nf++) {
                const int col = kb0 + nf * 8 + 2 * t;
#pragma unroll
                for (int e = 0; e < 2; e++) {
                    float v0 = s[nf][e]     * ALPHA;
                    float v1 = s[nf][e + 2] * ALPHA;
                    if (diag) {
                        if (col + e > qrow)     v0 = -3.4e38f;
                        if (col + e > qrow + 8) v1 = -3.4e38f;
                    }
                    s[nf][e] = v0; s[nf][e + 2] = v1;
                    tm0 = fmaxf(tm0, v0); tm1 = fmaxf(tm1, v1);
                }
            }
            tm0 = fmaxf(tm0, __shfl_xor_sync(0xffffffffu, tm0, 1));
            tm0 = fmaxf(tm0, __shfl_xor_sync(0xffffffffu, tm0, 2));
            tm1 = fmaxf(tm1, __shfl_xor_sync(0xffffffffu, tm1, 1));
            tm1 = fmaxf(tm1, __shfl_xor_sync(0xffffffffu, tm1, 2));

            const float nmx0 = fmaxf(mx0, tm0), nmx1 = fmaxf(mx1, tm1);
            const float sc0 = expf(mx0 - nmx0), sc1 = expf(mx1 - nmx1);
            mx0 = nmx0; mx1 = nmx1;

            uint32_t pA[8][4];
            float ts0 = 0.0f, ts1 = 0.0f;
#pragma unroll
            for (int nf = 0; nf < 16; nf++) {
                float e0 = expf(s[nf][0] - mx0);
                float e1 = expf(s[nf][1] - mx0);
                float e2 = expf(s[nf][2] - mx1);
                float e3 = expf(s[nf][3] - mx1);
                ts0 += e0 + e1; ts1 += e2 + e3;
                const int kc2 = nf >> 1, hi = nf & 1;
                pA[kc2][hi * 2]     = pk2h(e0, e1);
                pA[kc2][hi * 2 + 1] = pk2h(e2, e3);
            }
            ts0 += __shfl_xor_sync(0xffffffffu, ts0, 1);
            ts0 += __shfl_xor_sync(0xffffffffu, ts0, 2);
            ts1 += __shfl_xor_sync(0xffffffffu, ts1, 1);
            ts1 += __shfl_xor_sync(0xffffffffu, ts1, 2);
            sum0 = sum0 * sc0 + ts0;
            sum1 = sum1 * sc1 + ts1;

#pragma unroll
            for (int nf = 0; nf < 10; nf++) {
                o[nf][0] *= sc0; o[nf][1] *= sc0;
                o[nf][2] *= sc1; o[nf][3] *= sc1;
            }
#pragma unroll
            for (int nfp2 = 0; nfp2 < 5; nfp2++) {
#pragma unroll
                for (int kc2 = 0; kc2 < 8; kc2++) {
                    uint32_t b[4];
                    ldsm_x4_t(b[0], b[1], b[2], b[3],
                              vb + (kc2 * 16 + vrow) * 176
                                 + (nfp2 * 16 + vcol) * 2);
                    mma_f16(o[2 * nfp2],     pA[kc2], b[0], b[1]);
                    mma_f16(o[2 * nfp2 + 1], pA[kc2], b[2], b[3]);
                }
            }

            __syncthreads();
            if (j + 2 <= qt) { fillKV(j + 2); CP_COMMIT(); }
        }

        const float inv0 = 1.0f / sum0, inv1 = 1.0f / sum1;
        const long long r0 = (qtok0 + wr0 + g) * DD + zh * DHH;
        const long long r1 = r0 + 8LL * DD;
#pragma unroll
        for (int nf = 0; nf < 10; nf++) {
            const int d = nf * 8 + 2 * t;
            *(uint32_t*)(ctx + r0 + d) = pk2h(o[nf][0] * inv0, o[nf][1] * inv0);
            *(uint32_t*)(ctx + r1 + d) = pk2h(o[nf][2] * inv1, o[nf][3] * inv1);
        }
    }
}

// ---------------------------------------------------------------------------
// fp16 GEMM, K-chunk 64: C = alpha*A@B^T [+bias][relu][+resid].
// Row stride 176B (128B data + 48 pad): conflict-free ldsm.
// ---------------------------------------------------------------------------
template <int MW, int NW, bool RELU, bool HOUT>
__global__ void __launch_bounds__(MW * NW * 32)
gemm1(const hf* __restrict__ A, const hf* __restrict__ B,
      float* __restrict__ C, hf* __restrict__ Ch,
      const float* __restrict__ bias, const float* __restrict__ resid,
      int M, int N, int K, int lda, int ldb, int ldc, float alpha) {
    constexpr int AR  = 64 * MW;
    constexpr int BR  = 64 * NW;
    constexpr int BD  = MW * NW * 32;
    constexpr int A_OF = 0;
    constexpr int B_OF = AR * 176;
    constexpr int STG  = (AR + BR) * 176;

    const int m0 = blockIdx.y * AR;
    const int n0 = blockIdx.x * BR;

    extern __shared__ char sm[];
    const uint32_t smb = smem_u32(sm);

    const int tid  = threadIdx.x;
    const int wid  = tid >> 5;
    const int lane = tid & 31;
    const int wm   = wid / NW;
    const int wn   = wid % NW;

    const int nst = (K + 63) >> 6;

    auto fill = [&](int s) {
        const uint32_t sb = smb + (uint32_t)((s & 1) * STG);
        const int kbase = s << 6;
#pragma unroll
        for (int i = tid; i < AR * 8; i += BD) {
            const int row = i >> 3, c = i & 7;
            const long long go = (long long)(m0 + row) * lda + kbase + (c << 3);
            cp16(sb + row * 176 + c * 16 + A_OF, A + go, 16);
        }
#pragma unroll
        for (int i = tid; i < BR * 8; i += BD) {
            const int row = i >> 3, c = i & 7;
            const int sz  = ((n0 + row) < N) ? 16 : 0;
            const long long go = (long long)(n0 + row) * ldb + kbase + (c << 3);
            cp16(sb + row * 176 + c * 16 + B_OF, B + (sz ? go : 0), sz);
        }
    };

    float acc[4][8][4] = {};

    fill(0);
    CP_COMMIT();

    const int lrow = lane & 15;
    const int lcol = (lane >> 4) << 3;

    for (int s = 0; s < nst; s++) {
        CP_WAIT0();
        __syncthreads();
        if (s + 1 < nst) { fill(s + 1); CP_COMMIT(); }

        const uint32_t sb = smb + (uint32_t)((s & 1) * STG);
#pragma unroll
        for (int ks = 0; ks < 4; ks++) {
            const int kk = ks << 4;
            uint32_t af[4][4];
#pragma unroll
            for (int mf = 0; mf < 4; mf++) {
                uint32_t ra = sb + (uint32_t)((wm * 64 + mf * 16 + lrow) * 176
                                              + (kk + lcol) * 2);
                ldsm_x4(af[mf][0], af[mf][1], af[mf][2], af[mf][3], ra + A_OF);
            }
#pragma unroll
            for (int nfp = 0; nfp < 4; nfp++) {
                uint32_t rb = sb + (uint32_t)((wn * 64 + nfp * 16 + lrow) * 176
                                              + (kk + lcol) * 2);
                uint32_t bh[4];
                ldsm_x4(bh[0], bh[1], bh[2], bh[3], rb + B_OF);
#pragma unroll
                for (int mf = 0; mf < 4; mf++) {
                    mma_f16(acc[mf][2 * nfp],     af[mf], bh[0], bh[2]);
                    mma_f16(acc[mf][2 * nfp + 1], af[mf], bh[1], bh[3]);
                }
            }
        }
    }

    const int g = lane >> 2;
    const int t = lane & 3;
#pragma unroll
    for (int mf = 0; mf < 4; mf++) {
        const int gm0 = m0 + wm * 64 + mf * 16 + g;
        const long long ro0 = (long long)gm0 * ldc;
        const long long ro1 = ro0 + 8LL * ldc;
#pragma unroll
        for (int nf = 0; nf < 8; nf++) {
            const int gn = n0 + wn * 64 + nf * 8 + t * 2;
            if (gn < N) {
                float c0 = acc[mf][nf][0] * alpha;
                float c1 = acc[mf][nf][1] * alpha;
                float c2 = acc[mf][nf][2] * alpha;
                float c3 = acc[mf][nf][3] * alpha;
                if (bias) {
                    float b0 = bias[gn], b1 = bias[gn + 1];
                    c0 += b0; c1 += b1; c2 += b0; c3 += b1;
                }
                if (RELU) {
                    c0 = fmaxf(c0, 0.0f); c1 = fmaxf(c1, 0.0f);
                    c2 = fmaxf(c2, 0.0f); c3 = fmaxf(c3, 0.0f);
                }
                if (!HOUT) {
                    if (resid) {
                        c0 += resid[ro0 + gn]; c1 += resid[ro0 + gn + 1];
                        c2 += resid[ro1 + gn]; c3 += resid[ro1 + gn + 1];
                    }
                    *(float2*)(C + ro0 + gn) = make_float2(c0, c1);
                    *(float2*)(C + ro1 + gn) = make_float2(c2, c3);
                } else {
                    *(uint32_t*)(Ch + ro0 + gn) = pk2h(c0, c1);
                    *(uint32_t*)(Ch + ro1 + gn) = pk2h(c2, c3);
                }
            }
        }
    }
}

#define SM22 (2 * (128 + 128) * 176)   // 90112
#define SM12 (2 * (64 + 128) * 176)    // 67584

// ---------------------------------------------------------------------------
// Host launcher (graph-capturable: kernel launches only)
// ---------------------------------------------------------------------------
extern "C" void kernel_launch(void* const* d_in, const int* in_sizes, int n_in,
                              void* d_out, int out_size) {
    const unsigned int* idw = (const unsigned int*)d_in[0];
    const float* emb  = (const float*)d_in[1];
    const float* Wq   = (const float*)d_in[2];
    const float* Wk   = (const float*)d_in[3];
    const float* Wv   = (const float*)d_in[4];
    const float* Wo   = (const float*)d_in[5];
    const float* pbq  = (const float*)d_in[6];
    const float* pbk  = (const float*)d_in[7];
    const float* pbv  = (const float*)d_in[8];
    const float* pbo  = (const float*)d_in[9];
    const float* W1   = (const float*)d_in[10];
    const float* pb1  = (const float*)d_in[11];
    const float* W2   = (const float*)d_in[12];
    const float* pb2  = (const float*)d_in[13];
    const float* ln1g = (const float*)d_in[14];
    const float* ln1b = (const float*)d_in[15];
    const float* ln2g = (const float*)d_in[16];
    const float* ln2b = (const float*)d_in[17];
    const float* lnfg = (const float*)d_in[18];
    const float* lnfb = (const float*)d_in[19];

    float *px, *pbqkv;
    hf *pn, *pqkv, *pc, *ph1;
    hf *pwqkv, *pwo, *pw1, *pw2;
    cudaGetSymbolAddress((void**)&px,    g_x);
    cudaGetSymbolAddress((void**)&pbqkv, g_bqkv);
    cudaGetSymbolAddress((void**)&pn,    g_n);
    cudaGetSymbolAddress((void**)&pqkv,  g_qkv);
    cudaGetSymbolAddress((void**)&pc,    g_c);
    cudaGetSymbolAddress((void**)&ph1,   g_h1);
    cudaGetSymbolAddress((void**)&pwqkv, g_wqkv);
    cudaGetSymbolAddress((void**)&pwo,   g_wo);
    cudaGetSymbolAddress((void**)&pw1,   g_w1);
    cudaGetSymbolAddress((void**)&pw2,   g_w2);

    cudaFuncSetAttribute(gemm1<2, 2, false, true>,
                         cudaFuncAttributeMaxDynamicSharedMemorySize, SM22);
    cudaFuncSetAttribute(gemm1<2, 2, true,  true>,
                         cudaFuncAttributeMaxDynamicSharedMemorySize, SM22);
    cudaFuncSetAttribute(gemm1<1, 2, false, false>,
                         cudaFuncAttributeMaxDynamicSharedMemorySize, SM12);
    cudaFuncSetAttribute(flash_kernel,
                         cudaFuncAttributeMaxDynamicSharedMemorySize, SMEM_FLASH);

    detect_kernel<<<1, 256>>>(idw);
    embed_kernel<<<(MM * DD + 255) / 256, 256>>>(idw, emb, px);

    {
        // all DDxDD weight transposes (Wq/Wk/Wv/Wo x L) in one launch
        wtrans4_kernel<<<dim3(DD / 64, DD / 64, 4 * LL), 256>>>(
            Wq, Wk, Wv, Wo, pwqkv, pwo);
        wtrans_kernel<<<dim3(DFF / 64, DD / 64, LL), 256>>>(W1, pw1, DD, DFF,
                                                            (size_t)DD * DFF);
        wtrans_kernel<<<dim3(DD / 64, DFF / 64, LL), 256>>>(W2, pw2, DFF, DD,
                                                            (size_t)DFF * DD);
        packb_kernel<<<(LL * 3 * DD + 255) / 256, 256>>>(pbq, pbk, pbv, pbqkv);
    }

    const dim3 gQKV(D3 / 128, MM / 128);         // 480
    const dim3 gN64(DD / 128, MM / 64);          // 320
    const dim3 gFF1(DFF / 128, MM / 128);        // 1024

    for (int l = 0; l < LL; l++) {
        const size_t woff4 = (size_t)l * DD * DD;
        const size_t woffQ = (size_t)l * 3 * DD * DD;
        const size_t woff1 = (size_t)l * DD * DFF;

        layernorm_kernel<true><<<MM, 160>>>(px, nullptr, pn,
                                            ln1g + l * DD, ln1b + l * DD);

        // fused qkv projection -> packed [MM, 3840] fp16
        gemm1<2, 2, false, true><<<gQKV, 128, SM22>>>(
            pn, pwqkv + woffQ, nullptr, pqkv,
            pbqkv + l * D3, nullptr,
            MM, D3, DD, DD, DD, D3, 1.0f);

        // fused attention
        flash_kernel<<<144, 256, SMEM_FLASH>>>(pqkv, pc);

        // x = x + ctx @ Wo + bo
        gemm1<1, 2, false, false><<<gN64, 64, SM12>>>(
            pc, pwo + woff4, px, nullptr,
            pbo + l * DD, px,
            MM, DD, DD, DD, DD, DD, 1.0f);

        layernorm_kernel<true><<<MM, 160>>>(px, nullptr, pn,
                                            ln2g + l * DD, ln2b + l * DD);

        // h1 = relu(n @ W1 + b1) -> fp16
        gemm1<2, 2, true, true><<<gFF1, 128, SM22>>>(
            pn, pw1 + woff1, nullptr, ph1,
            pb1 + l * DFF, nullptr,
            MM, DFF, DD, DD, DD, DFF, 1.0f);

        // x = x + h1 @ W2 + b2
        gemm1<1, 2, false, false><<<gN64, 64, SM12>>>(
            ph1, pw2 + woff1, px, nullptr,
            pb2 + l * DD, px,
            MM, DD, DFF, DFF, DFF, DD, 1.0f);
    }

    layernorm_kernel<false><<<MM, 160>>>(px, (float*)d_out, nullptr,
                                         lnfg, lnfb);
}